// round 8
// baseline (speedup 1.0000x reference)
#include <cuda_runtime.h>
#include <cuda_fp16.h>
#include <cstdint>
#include <math.h>

// ---------------------------------------------------------------------------
// Problem constants
// ---------------------------------------------------------------------------
#define BATCH   4096
#define DIN     128
#define DOUT    128
#define NB      9
#define KPAD    10                 // k per input dim, padded 9 -> 10 (slot 9 = 0)
#define KTOT    (DIN * KPAD)       // 1280
#define KSPLIT  8
#define ISL     (DIN / KSPLIT)     // 16 input dims per split
#define KSLICE  (ISL * KPAD)       // 160 k per split
#define BM      64
#define NTILE   (BATCH / BM)       // 64
#define FCH     8                  // input dims per feat chunk
#define NCH     (ISL / FCH)        // 2 chunks
#define KCH     (FCH * KPAD)       // 80 k rows per chunk (5 k16-steps)

// smem strides (halves).
// ASTR: 72h = 144B = 36w === 4 banks/row -> ldmatrix conflict-free.
// BSTR: 168h = 336B = 84w === 20 banks/row -> conflict-free; 336 % 16 == 0.
#define ASTR    72
#define BSTR    168

// smem layout (bytes)
#define OFF_XS  0
#define XS_B    (BM * 17 * 4)               // 4352
#define OFF_BS  (OFF_XS + XS_B)
#define BS_B    (DOUT * BSTR * 2)           // 43008
#define OFF_AS  (OFF_BS + BS_B)
#define AS_STG  (KCH * ASTR * 2)            // 11520 per stage
#define AS_B    (2 * AS_STG)                // 23040 (double-buffered)
#define OFF_BP  (OFF_AS + AS_B)
#define BP_B    (DOUT * 4)                  // 512
#define SMEM_BYTES (OFF_BP + BP_B)          // 70912 -> 3 CTAs/SM

// ---------------------------------------------------------------------------
// Device scratch (allocation-free)
// ---------------------------------------------------------------------------
__device__ __half g_Wh[DOUT * KTOT];              // fp16 W*C, [o][k], 320 KB
__device__ float  g_part[KSPLIT * BATCH * DOUT];  // 16 MB fp32 partials
__device__ int    g_cnt[NTILE];                   // zero-init; reset by reducer

// ---------------------------------------------------------------------------
// Helpers
// ---------------------------------------------------------------------------
__device__ __forceinline__ float tanh_ap(float f) {
    float r; asm("tanh.approx.f32 %0, %1;" : "=f"(r) : "f"(f)); return r;
}
__device__ __forceinline__ float sqrt_ap(float f) {
    float r; asm("sqrt.approx.f32 %0, %1;" : "=f"(r) : "f"(f)); return r;
}
__device__ __forceinline__ uint32_t s2u(const void* p) {
    uint32_t a;
    asm("{ .reg .u64 t; cvta.to.shared.u64 t, %1; cvt.u32.u64 %0, t; }" : "=r"(a) : "l"(p));
    return a;
}
__device__ __forceinline__ void cp16(uint32_t dst, const void* src) {
    asm volatile("cp.async.cg.shared.global [%0], [%1], 16;" :: "r"(dst), "l"(src) : "memory");
}
#define CP_COMMIT() asm volatile("cp.async.commit_group;" ::: "memory")
#define CP_WAIT0()  asm volatile("cp.async.wait_group 0;"  ::: "memory")

__device__ __forceinline__ void ldm_x4(uint32_t* r, uint32_t addr) {
    asm volatile("ldmatrix.sync.aligned.m8n8.x4.shared.b16 {%0,%1,%2,%3}, [%4];"
        : "=r"(r[0]), "=r"(r[1]), "=r"(r[2]), "=r"(r[3]) : "r"(addr));
}
__device__ __forceinline__ void ldm_x4t(uint32_t* r, uint32_t addr) {
    asm volatile("ldmatrix.sync.aligned.m8n8.x4.trans.shared.b16 {%0,%1,%2,%3}, [%4];"
        : "=r"(r[0]), "=r"(r[1]), "=r"(r[2]), "=r"(r[3]) : "r"(addr));
}
// m16n8k16 fp16 mma, fp32 accumulate
__device__ __forceinline__ void mma_f16(float* d, const uint32_t* a, uint32_t b0, uint32_t b1) {
    asm volatile(
        "mma.sync.aligned.m16n8k16.row.col.f32.f16.f16.f32 "
        "{%0,%1,%2,%3}, {%4,%5,%6,%7}, {%8,%9}, {%0,%1,%2,%3};"
        : "+f"(d[0]), "+f"(d[1]), "+f"(d[2]), "+f"(d[3])
        : "r"(a[0]), "r"(a[1]), "r"(a[2]), "r"(a[3]), "r"(b0), "r"(b1));
}

// ---------------------------------------------------------------------------
// Prep: g_Wh[o][i*10 + 2p .. 2p+1] = fp16(W[i,o,kb]*C[i,o]); slot 9 = 0.
// ---------------------------------------------------------------------------
__global__ void kan_prep(const float* __restrict__ W, const float* __restrict__ C) {
    int j = blockIdx.x * blockDim.x + threadIdx.x;   // 0 .. 81919
    int p  = j % 5;
    int io = j / 5;                 // i*128 + o
    if (io >= DIN * DOUT) return;
    int o = io & 127;
    int i = io >> 7;
    float cv = C[io];
    const float* wp = W + (size_t)io * NB + p * 2;
    float v0 = wp[0] * cv;
    float v1 = (p < 4) ? wp[1] * cv : 0.0f;
    ((__half2*)g_Wh)[o * (KTOT / 2) + i * (KPAD / 2) + p] = __floats2half2_rn(v0, v1);
}

// ---------------------------------------------------------------------------
// Feat producer: 8 dims x 64 rows into one A stage (k-major, CF stores)
// ---------------------------------------------------------------------------
__device__ __forceinline__ void produce_feats(const float* Xs, __half* Ast,
                                              int c, int tid) {
    #pragma unroll
    for (int jj = 0; jj < 2; ++jj) {
        int j   = tid + jj * 256;
        int row = j & 63;
        int ii  = j >> 6;            // 0..7
        float xv = Xs[row * 17 + c * FCH + ii];
        float ax = fabsf(xv);
        float x2 = xv * xv;
        __half* d = Ast + (ii * KPAD) * ASTR + row;
        d[0 * ASTR] = __float2half_rn(xv);
        d[1 * ASTR] = __float2half_rn(x2);
        d[2 * ASTR] = __float2half_rn(x2 * xv);
        d[3 * ASTR] = __float2half_rn(__expf(xv));
        d[4 * ASTR] = __float2half_rn(__logf(ax + 1.0f));
        d[5 * ASTR] = __float2half_rn(sqrt_ap(ax));
        d[6 * ASTR] = __float2half_rn(tanh_ap(xv));
        d[7 * ASTR] = __float2half_rn(__sinf(xv));
        d[8 * ASTR] = __float2half_rn(ax);
        d[9 * ASTR] = __half(0.0f);
    }
}

// ---------------------------------------------------------------------------
// Main: fused basis + fp16 ldmatrix mma; full B slice prefetched; A double-
// buffered (produce c+1 overlaps mma c in one barrier interval); split-K=8.
// Grid (64 tiles, 8 splits) = 512 blocks, 256 threads, 3 CTAs/SM.
// ---------------------------------------------------------------------------
__global__ __launch_bounds__(256, 3)
void kan_main(const float* __restrict__ x, const float* __restrict__ bias,
              const float* __restrict__ C, float* __restrict__ out)
{
    extern __shared__ char smem[];
    float*  Xs = (float*)(smem + OFF_XS);      // [64][17]
    __half* Bs = (__half*)(smem + OFF_BS);     // [128 n][168], cols 0..159 data
    __half* As = (__half*)(smem + OFF_AS);     // 2 stages of [80 k][72 m]
    float*  Bp = (float*)(smem + OFF_BP);      // [128] beta partials
    __shared__ int s_last;

    const int tid   = threadIdx.x;
    const int lane  = tid & 31;
    const int warp  = tid >> 5;
    const int wm    = warp & 1;          // m warp -> m0 = wm*32
    const int wn    = warp >> 1;         // n warp -> n0 = wn*32
    const int g     = lane >> 2;
    const int tg    = lane & 3;
    const int t4    = lane >> 3;
    const int r8    = lane & 7;
    const int tile  = blockIdx.x;
    const int split = blockIdx.y;
    const int bm0   = tile * BM;
    const int i0    = split * ISL;

    // --- cp.async the fp16 B slice [128 n][160 k]: 2560 x 16B
    {
        const uint32_t bsb = s2u(Bs);
        const __half*  src0 = g_Wh + (size_t)split * KSLICE;
        #pragma unroll
        for (int jj = 0; jj < 10; ++jj) {
            int j = tid + jj * 256;
            int n = j / 20, q = j - n * 20;
            cp16(bsb + (uint32_t)(n * (BSTR * 2) + q * 16),
                 src0 + (size_t)n * KTOT + q * 8);
        }
        CP_COMMIT();
    }

    // --- stage X tile [64 rows][16 i]
    {
        int r = tid >> 2, q = tid & 3;
        float4 v = *(const float4*)(x + (size_t)(bm0 + r) * DIN + i0 + q * 4);
        float* d = Xs + r * 17 + q * 4;
        d[0] = v.x; d[1] = v.y; d[2] = v.z; d[3] = v.w;
    }

    // --- this split's beta slice
    if (tid < DOUT) {
        float s = 0.0f;
        #pragma unroll
        for (int ii = 0; ii < ISL; ++ii)
            s += bias[(i0 + ii) * DOUT + tid] * C[(i0 + ii) * DOUT + tid];
        Bp[tid] = s;
    }

    // --- ldmatrix lane base addresses
    uint32_t aAddr[2], bAddr[2];
    {
        const uint32_t asb = s2u(As), bsb = s2u(Bs);
        #pragma unroll
        for (int mt = 0; mt < 2; ++mt) {
            int m0 = wm * 32 + mt * 16;
            aAddr[mt] = asb + (uint32_t)(((t4 >> 1) * 8 + r8) * ASTR + m0 + (t4 & 1) * 8) * 2;
        }
        #pragma unroll
        for (int p = 0; p < 2; ++p) {
            int n = wn * 32 + p * 16 + (t4 >> 1) * 8 + r8;
            bAddr[p] = bsb + (uint32_t)(n * BSTR + (t4 & 1) * 8) * 2;
        }
    }

    float acc[2][4][4];
    #pragma unroll
    for (int mt = 0; mt < 2; ++mt)
        #pragma unroll
        for (int nt = 0; nt < 4; ++nt)
            #pragma unroll
            for (int e = 0; e < 4; ++e) acc[mt][nt][e] = 0.0f;

    __syncthreads();   // Xs ready (Bp/B not needed yet)

    // --- chunk 0 feats into stage 0
    produce_feats(Xs, As, 0, tid);
    CP_WAIT0();
    __syncthreads();   // stage-0 feats + B slice visible

    #pragma unroll
    for (int c = 0; c < NCH; ++c) {
        // produce next chunk into the other stage (overlaps this chunk's mma)
        if (c + 1 < NCH)
            produce_feats(Xs, As + (c + 1) * (AS_STG / 2), c + 1, tid);

        // --- 5 k16-steps on stage c
        const uint32_t aStage = (uint32_t)(c * AS_STG);
        #pragma unroll
        for (int s5 = 0; s5 < 5; ++s5) {
            const uint32_t kaOff = aStage + (uint32_t)(s5 * 16 * ASTR) * 2;
            const uint32_t kbOff = (uint32_t)((c * KCH + s5 * 16)) * 2;
            uint32_t a[2][4], bq[2][4];
            ldm_x4t(a[0], aAddr[0] + kaOff);
            ldm_x4t(a[1], aAddr[1] + kaOff);
            ldm_x4(bq[0], bAddr[0] + kbOff);
            ldm_x4(bq[1], bAddr[1] + kbOff);
            #pragma unroll
            for (int mt = 0; mt < 2; ++mt)
                #pragma unroll
                for (int nt = 0; nt < 4; ++nt)
                    mma_f16(acc[mt][nt], a[mt],
                            bq[nt >> 1][(nt & 1) * 2], bq[nt >> 1][(nt & 1) * 2 + 1]);
        }
        if (c + 1 < NCH) __syncthreads();   // next stage feats complete
    }

    // --- epilogue: add beta, write partials
    {
        float* base = g_part + (size_t)split * BATCH * DOUT;
        #pragma unroll
        for (int nt = 0; nt < 4; ++nt) {
            int col = wn * 32 + nt * 8 + tg * 2;
            float b0 = Bp[col];
            float b1 = Bp[col + 1];
            #pragma unroll
            for (int mt = 0; mt < 2; ++mt) {
                int row = bm0 + wm * 32 + mt * 16 + g;
                float* p = base + (size_t)row * DOUT + col;
                *(float2*)p              = make_float2(acc[mt][nt][0] + b0, acc[mt][nt][1] + b1);
                *(float2*)(p + 8 * DOUT) = make_float2(acc[mt][nt][2] + b0, acc[mt][nt][3] + b1);
            }
        }
    }

    // --- last split block of this tile reduces 8 partial planes -> out
    __threadfence();
    __syncthreads();
    if (tid == 0)
        s_last = (atomicAdd(&g_cnt[tile], 1) == KSPLIT - 1);
    __syncthreads();

    if (s_last) {
        __threadfence();
        const float4* pp = (const float4*)g_part;
        const size_t plane = (size_t)BATCH * DOUT / 4;
        const size_t base4 = (size_t)bm0 * (DOUT / 4);
        #pragma unroll
        for (int idx = tid; idx < BM * DOUT / 4; idx += 256) {
            size_t o = base4 + idx;
            float4 s = __ldcg(pp + o);
            #pragma unroll
            for (int sp = 1; sp < KSPLIT; ++sp) {
                float4 p = __ldcg(pp + sp * plane + o);
                s.x += p.x; s.y += p.y; s.z += p.z; s.w += p.w;
            }
            ((float4*)out)[o] = s;
        }
        __syncthreads();
        if (tid == 0) g_cnt[tile] = 0;   // reset for next graph replay
    }
}

// ---------------------------------------------------------------------------
extern "C" void kernel_launch(void* const* d_in, const int* in_sizes, int n_in,
                              void* d_out, int out_size) {
    const float* x    = (const float*)d_in[0];   // [4096,128]
    const float* W    = (const float*)d_in[1];   // [128,128,9]
    const float* bias = (const float*)d_in[2];   // [128,128]
    const float* C    = (const float*)d_in[3];   // [128,128]
    float* out        = (float*)d_out;           // [4096,128]
    (void)in_sizes; (void)n_in; (void)out_size;

    cudaFuncSetAttribute(kan_main, cudaFuncAttributeMaxDynamicSharedMemorySize, SMEM_BYTES);

    kan_prep<<<320, 256>>>(W, C);
    kan_main<<<dim3(NTILE, KSPLIT), 256, SMEM_BYTES>>>(x, bias, C, out);
}

// round 9
// speedup vs baseline: 1.0742x; 1.0742x over previous
#include <cuda_runtime.h>
#include <cuda_fp16.h>
#include <cstdint>
#include <math.h>

// ---------------------------------------------------------------------------
// Problem constants (R7 geometry — best measured — with MUFU-free feats)
// ---------------------------------------------------------------------------
#define BATCH   4096
#define DIN     128
#define DOUT    128
#define NB      9
#define KPAD    10                 // k per input dim, padded 9 -> 10 (slot 9 = 0)
#define KTOT    (DIN * KPAD)       // 1280
#define KSPLIT  4
#define ISL     (DIN / KSPLIT)     // 32 input dims per split
#define KSLICE  (ISL * KPAD)       // 320 k per split
#define BM      64
#define NTILE   (BATCH / BM)       // 64
#define FCH     8                  // input dims per feat chunk
#define NCH     (ISL / FCH)        // 4 chunks
#define KCH     (FCH * KPAD)       // 80 k rows per chunk (5 k16-steps)

#define ASTR    72                 // halves; 144B/row -> ldmatrix CF
#define BSTR    328                // halves; 656B/row -> CF, 16B-aligned

// smem layout (bytes)
#define OFF_XS  0
#define XS_B    (BM * 33 * 4)               // 8448
#define OFF_BS  (OFF_XS + XS_B)
#define BS_B    (DOUT * BSTR * 2)           // 83968
#define OFF_AS  (OFF_BS + BS_B)
#define AS_B    (KCH * ASTR * 2)            // 11520
#define OFF_BP  (OFF_AS + AS_B)
#define BP_B    (DOUT * 4)                  // 512
#define SMEM_BYTES (OFF_BP + BP_B)          // 104448 -> 2 CTAs/SM

// ---------------------------------------------------------------------------
// Device scratch (allocation-free)
// ---------------------------------------------------------------------------
__device__ __half g_Wh[DOUT * KTOT];              // fp16 W*C, [o][k], 320 KB
__device__ float  g_part[KSPLIT * BATCH * DOUT];  // 8 MB fp32 partials
__device__ int    g_cnt[NTILE];                   // zero-init; reset by reducer

// ---------------------------------------------------------------------------
// MUFU-free transcendental helpers (fp16-accuracy targets, FMA/ALU pipes only)
// ---------------------------------------------------------------------------
__device__ __forceinline__ float fast_rcp(float d) {      // d in [~1, 5e4]
    float r = __uint_as_float(0x7EF311C3u - __float_as_uint(d));
    r = r * fmaf(-d, r, 2.0f);
    r = r * fmaf(-d, r, 2.0f);
    r = r * fmaf(-d, r, 2.0f);
    return r;
}
__device__ __forceinline__ float fast_exp(float xv) {     // |xv| <~ 20
    float t  = xv * 1.44269504f;
    float tm = t + 12582912.0f;                 // rint via magic add
    int   ni = __float_as_int(tm);              // low bits hold the integer
    float n  = tm - 12582912.0f;
    float f  = t - n;                           // [-0.5, 0.5]
    float p  = 0.00133335581f;
    p = fmaf(p, f, 0.00961812911f);
    p = fmaf(p, f, 0.0555041087f);
    p = fmaf(p, f, 0.240226507f);
    p = fmaf(p, f, 0.693147181f);
    p = fmaf(p, f, 1.0f);
    return __int_as_float(__float_as_int(p) + (ni << 23));
}
__device__ __forceinline__ float fast_sqrt(float ax) {    // ax >= 0; ax=0 -> 0
    float y = __uint_as_float(0x5F3759DFu - (__float_as_uint(ax) >> 1));
    y = y * fmaf(-0.5f * ax, y * y, 1.5f);
    y = y * fmaf(-0.5f * ax, y * y, 1.5f);
    return ax * y;
}
__device__ __forceinline__ float fast_log1p(float ax) {   // ax >= 0
    float u  = ax + 1.0f;                        // [1, ~6.5]
    int   ub = __float_as_int(u);
    float ef = (float)((ub - 0x3F800000) >> 23); // exponent 0..2
    float m  = __int_as_float((ub & 0x007FFFFF) | 0x3F800000);  // [1,2)
    float t  = m - 1.0f;                         // [0,1)
    float s  = t * fast_rcp(t + 2.0f);           // [0, 1/3]
    float w  = s * s;
    float p  = fmaf(w, 0.142857143f, 0.2f);      // 1/7, 1/5
    p = fmaf(w, p, 0.333333333f);                // 1/3
    p = fmaf(w, p, 1.0f);
    return fmaf(ef, 0.693147181f, 2.0f * s * p);
}
__device__ __forceinline__ float fast_sin(float xv) {     // |xv| <~ 20
    float t  = xv * 0.318309886f;                // x / pi
    float tm = t + 12582912.0f;
    int   ni = __float_as_int(tm);
    float n  = tm - 12582912.0f;
    float f  = fmaf(n, -3.14159274f, xv);        // pi_hi
    f = fmaf(n, 8.742278e-8f, f);                // pi_lo correction
    float w  = f * f;
    float p  = fmaf(w, 2.75573192e-6f, -1.98412698e-4f);
    p = fmaf(w, p, 8.33333333e-3f);
    p = fmaf(w, p, -0.166666667f);
    p = fmaf(w, p, 1.0f);
    float s = f * p;
    return __int_as_float(__float_as_int(s) ^ ((ni & 1) << 31));
}

// ---------------------------------------------------------------------------
// PTX helpers
// ---------------------------------------------------------------------------
__device__ __forceinline__ uint32_t s2u(const void* p) {
    uint32_t a;
    asm("{ .reg .u64 t; cvta.to.shared.u64 t, %1; cvt.u32.u64 %0, t; }" : "=r"(a) : "l"(p));
    return a;
}
__device__ __forceinline__ void cp16(uint32_t dst, const void* src) {
    asm volatile("cp.async.cg.shared.global [%0], [%1], 16;" :: "r"(dst), "l"(src) : "memory");
}
#define CP_COMMIT() asm volatile("cp.async.commit_group;" ::: "memory")
#define CP_WAIT0()  asm volatile("cp.async.wait_group 0;"  ::: "memory")

__device__ __forceinline__ void ldm_x4(uint32_t* r, uint32_t addr) {
    asm volatile("ldmatrix.sync.aligned.m8n8.x4.shared.b16 {%0,%1,%2,%3}, [%4];"
        : "=r"(r[0]), "=r"(r[1]), "=r"(r[2]), "=r"(r[3]) : "r"(addr));
}
__device__ __forceinline__ void ldm_x4t(uint32_t* r, uint32_t addr) {
    asm volatile("ldmatrix.sync.aligned.m8n8.x4.trans.shared.b16 {%0,%1,%2,%3}, [%4];"
        : "=r"(r[0]), "=r"(r[1]), "=r"(r[2]), "=r"(r[3]) : "r"(addr));
}
__device__ __forceinline__ void mma_f16(float* d, const uint32_t* a, uint32_t b0, uint32_t b1) {
    asm volatile(
        "mma.sync.aligned.m16n8k16.row.col.f32.f16.f16.f32 "
        "{%0,%1,%2,%3}, {%4,%5,%6,%7}, {%8,%9}, {%0,%1,%2,%3};"
        : "+f"(d[0]), "+f"(d[1]), "+f"(d[2]), "+f"(d[3])
        : "r"(a[0]), "r"(a[1]), "r"(a[2]), "r"(a[3]), "r"(b0), "r"(b1));
}

// ---------------------------------------------------------------------------
// Prep: g_Wh[o][i*10 + 2p .. 2p+1] = fp16(W[i,o,kb]*C[i,o]); slot 9 = 0.
// ---------------------------------------------------------------------------
__global__ void kan_prep(const float* __restrict__ W, const float* __restrict__ C) {
    int j = blockIdx.x * blockDim.x + threadIdx.x;   // 0 .. 81919
    int p  = j % 5;
    int io = j / 5;                 // i*128 + o
    if (io >= DIN * DOUT) return;
    int o = io & 127;
    int i = io >> 7;
    float cv = C[io];
    const float* wp = W + (size_t)io * NB + p * 2;
    float v0 = wp[0] * cv;
    float v1 = (p < 4) ? wp[1] * cv : 0.0f;
    ((__half2*)g_Wh)[o * (KTOT / 2) + i * (KPAD / 2) + p] = __floats2half2_rn(v0, v1);
}

// ---------------------------------------------------------------------------
// Main: fused basis (MUFU-free) + fp16 ldmatrix mma; B slice prefetched;
// split-K=4, fused last-block reduction. Grid (64, 4), 256 thr, 2 CTAs/SM.
// ---------------------------------------------------------------------------
__global__ __launch_bounds__(256, 2)
void kan_main(const float* __restrict__ x, const float* __restrict__ bias,
              const float* __restrict__ C, float* __restrict__ out)
{
    extern __shared__ char smem[];
    float*  Xs = (float*)(smem + OFF_XS);      // [64][33]
    __half* Bs = (__half*)(smem + OFF_BS);     // [128 n][328], cols 0..319 data
    __half* As = (__half*)(smem + OFF_AS);     // [80 k][72 m] (k-major)
    float*  Bp = (float*)(smem + OFF_BP);      // [128] beta partials
    __shared__ int s_last;

    const int tid   = threadIdx.x;
    const int lane  = tid & 31;
    const int warp  = tid >> 5;
    const int wm    = warp & 1;
    const int wn    = warp >> 1;
    const int g     = lane >> 2;
    const int tg    = lane & 3;
    const int t4    = lane >> 3;
    const int r8    = lane & 7;
    const int tile  = blockIdx.x;
    const int split = blockIdx.y;
    const int bm0   = tile * BM;
    const int i0    = split * ISL;

    // --- cp.async the fp16 B slice [128 n][320 k]: 5120 x 16B
    {
        const uint32_t bsb = s2u(Bs);
        const __half*  src0 = g_Wh + (size_t)split * KSLICE;
        #pragma unroll
        for (int jj = 0; jj < 20; ++jj) {
            int j = tid + jj * 256;
            int n = j / 40, q = j - n * 40;
            cp16(bsb + (uint32_t)(n * (BSTR * 2) + q * 16),
                 src0 + (size_t)n * KTOT + q * 8);
        }
        CP_COMMIT();
    }

    // --- stage X tile [64 rows][32 i]
    #pragma unroll
    for (int jj = 0; jj < 2; ++jj) {
        int j = tid + jj * 256;
        int r = j >> 3, q = j & 7;
        float4 v = *(const float4*)(x + (size_t)(bm0 + r) * DIN + i0 + q * 4);
        float* d = Xs + r * 33 + q * 4;
        d[0] = v.x; d[1] = v.y; d[2] = v.z; d[3] = v.w;
    }

    // --- this split's beta slice
    if (tid < DOUT) {
        float s = 0.0f;
        #pragma unroll 8
        for (int ii = 0; ii < ISL; ++ii)
            s += bias[(i0 + ii) * DOUT + tid] * C[(i0 + ii) * DOUT + tid];
        Bp[tid] = s;
    }

    // --- ldmatrix lane base addresses
    uint32_t aAddr[2], bAddr[2];
    {
        const uint32_t asb = s2u(As), bsb = s2u(Bs);
        #pragma unroll
        for (int mt = 0; mt < 2; ++mt) {
            int m0 = wm * 32 + mt * 16;
            aAddr[mt] = asb + (uint32_t)(((t4 >> 1) * 8 + r8) * ASTR + m0 + (t4 & 1) * 8) * 2;
        }
        #pragma unroll
        for (int p = 0; p < 2; ++p) {
            int n = wn * 32 + p * 16 + (t4 >> 1) * 8 + r8;
            bAddr[p] = bsb + (uint32_t)(n * BSTR + (t4 & 1) * 8) * 2;
        }
    }

    float acc[2][4][4];
    #pragma unroll
    for (int mt = 0; mt < 2; ++mt)
        #pragma unroll
        for (int nt = 0; nt < 4; ++nt)
            #pragma unroll
            for (int e = 0; e < 4; ++e) acc[mt][nt][e] = 0.0f;

    __syncthreads();   // Xs, Bp ready

    #pragma unroll
    for (int c = 0; c < NCH; ++c) {
        if (c) __syncthreads();

        // --- feats: 8 dims x 64 rows, 2 per thread, ALL on FMA/ALU pipes
        #pragma unroll
        for (int jj = 0; jj < 2; ++jj) {
            int j   = tid + jj * 256;
            int row = j & 63;
            int ii  = j >> 6;
            float xv = Xs[row * 33 + c * FCH + ii];
            float ax = fabsf(xv);
            float x2 = xv * xv;
            float ee = fast_exp(xv);
            float E  = ee * ee;                              // e^{2x}
            float th = fmaf(-2.0f, fast_rcp(E + 1.0f), 1.0f);
            __half* d = As + (ii * KPAD) * ASTR + row;
            d[0 * ASTR] = __float2half_rn(xv);
            d[1 * ASTR] = __float2half_rn(x2);
            d[2 * ASTR] = __float2half_rn(x2 * xv);
            d[3 * ASTR] = __float2half_rn(ee);
            d[4 * ASTR] = __float2half_rn(fast_log1p(ax));
            d[5 * ASTR] = __float2half_rn(fast_sqrt(ax));
            d[6 * ASTR] = __float2half_rn(th);
            d[7 * ASTR] = __float2half_rn(fast_sin(xv));
            d[8 * ASTR] = __float2half_rn(ax);
            d[9 * ASTR] = __half(0.0f);
        }
        if (c == 0) CP_WAIT0();
        __syncthreads();

        // --- 5 k16-steps
        #pragma unroll
        for (int s5 = 0; s5 < 5; ++s5) {
            const uint32_t kaOff = (uint32_t)(s5 * 16 * ASTR) * 2;
            const uint32_t kbOff = (uint32_t)((c * KCH + s5 * 16)) * 2;
            uint32_t a[2][4], bq[2][4];
            ldm_x4t(a[0], aAddr[0] + kaOff);
            ldm_x4t(a[1], aAddr[1] + kaOff);
            ldm_x4(bq[0], bAddr[0] + kbOff);
            ldm_x4(bq[1], bAddr[1] + kbOff);
            #pragma unroll
            for (int mt = 0; mt < 2; ++mt)
                #pragma unroll
                for (int nt = 0; nt < 4; ++nt)
                    mma_f16(acc[mt][nt], a[mt],
                            bq[nt >> 1][(nt & 1) * 2], bq[nt >> 1][(nt & 1) * 2 + 1]);
        }
    }

    // --- epilogue: add beta, write partials
    {
        float* base = g_part + (size_t)split * BATCH * DOUT;
        #pragma unroll
        for (int nt = 0; nt < 4; ++nt) {
            int col = wn * 32 + nt * 8 + tg * 2;
            float b0 = Bp[col];
            float b1 = Bp[col + 1];
            #pragma unroll
            for (int mt = 0; mt < 2; ++mt) {
                int row = bm0 + wm * 32 + mt * 16 + g;
                float* p = base + (size_t)row * DOUT + col;
                *(float2*)p              = make_float2(acc[mt][nt][0] + b0, acc[mt][nt][1] + b1);
                *(float2*)(p + 8 * DOUT) = make_float2(acc[mt][nt][2] + b0, acc[mt][nt][3] + b1);
            }
        }
    }

    // --- last split block of this tile reduces 4 partial planes -> out
    __threadfence();
    __syncthreads();
    if (tid == 0)
        s_last = (atomicAdd(&g_cnt[tile], 1) == KSPLIT - 1);
    __syncthreads();

    if (s_last) {
        __threadfence();
        const float4* pp = (const float4*)g_part;
        const size_t plane = (size_t)BATCH * DOUT / 4;
        const size_t base4 = (size_t)bm0 * (DOUT / 4);
        #pragma unroll
        for (int idx = tid; idx < BM * DOUT / 4; idx += 256) {
            size_t o = base4 + idx;
            float4 p0 = __ldcg(pp + o);
            float4 p1 = __ldcg(pp + plane + o);
            float4 p2 = __ldcg(pp + 2 * plane + o);
            float4 p3 = __ldcg(pp + 3 * plane + o);
            float4 s;
            s.x = (p0.x + p1.x) + (p2.x + p3.x);
            s.y = (p0.y + p1.y) + (p2.y + p3.y);
            s.z = (p0.z + p1.z) + (p2.z + p3.z);
            s.w = (p0.w + p1.w) + (p2.w + p3.w);
            ((float4*)out)[o] = s;
        }
        __syncthreads();
        if (tid == 0) g_cnt[tile] = 0;
    }
}

// ---------------------------------------------------------------------------
extern "C" void kernel_launch(void* const* d_in, const int* in_sizes, int n_in,
                              void* d_out, int out_size) {
    const float* x    = (const float*)d_in[0];   // [4096,128]
    const float* W    = (const float*)d_in[1];   // [128,128,9]
    const float* bias = (const float*)d_in[2];   // [128,128]
    const float* C    = (const float*)d_in[3];   // [128,128]
    float* out        = (float*)d_out;           // [4096,128]
    (void)in_sizes; (void)n_in; (void)out_size;

    cudaFuncSetAttribute(kan_main, cudaFuncAttributeMaxDynamicSharedMemorySize, SMEM_BYTES);

    kan_prep<<<320, 256>>>(W, C);
    kan_main<<<dim3(NTILE, KSPLIT), 256, SMEM_BYTES>>>(x, bias, C, out);
}

// round 10
// speedup vs baseline: 1.1250x; 1.0473x over previous
#include <cuda_runtime.h>
#include <cuda_fp16.h>
#include <cstdint>
#include <math.h>

// ---------------------------------------------------------------------------
// Problem constants (R7 geometry + overlapped produce/mma, no Xs staging)
// ---------------------------------------------------------------------------
#define BATCH   4096
#define DIN     128
#define DOUT    128
#define NB      9
#define KPAD    10                 // k per input dim, padded 9 -> 10 (slot 9 = 0)
#define KTOT    (DIN * KPAD)       // 1280
#define KSPLIT  4
#define ISL     (DIN / KSPLIT)     // 32 input dims per split
#define KSLICE  (ISL * KPAD)       // 320 k per split
#define BM      64
#define NTILE   (BATCH / BM)       // 64
#define FCH     8                  // input dims per feat chunk
#define NCH     (ISL / FCH)        // 4 chunks
#define KCH     (FCH * KPAD)       // 80 k rows per chunk (5 k16-steps)

#define ASTR    72                 // halves; 144B/row -> ldmatrix CF
#define BSTR    328                // halves; 656B/row -> CF, 16B-aligned

// smem layout (bytes)
#define OFF_BS  0
#define BS_B    (DOUT * BSTR * 2)           // 83968
#define OFF_AS  (OFF_BS + BS_B)
#define AS_STG  (KCH * ASTR * 2)            // 11520 bytes per stage
#define AS_B    (2 * AS_STG)                // 23040 (double-buffered)
#define OFF_BP  (OFF_AS + AS_B)
#define BP_B    (DOUT * 4)                  // 512
#define SMEM_BYTES (OFF_BP + BP_B)          // 107520 -> 2 CTAs/SM

// ---------------------------------------------------------------------------
// Device scratch (allocation-free)
// ---------------------------------------------------------------------------
__device__ __half g_Wh[DOUT * KTOT];              // fp16 W*C, [o][k], 320 KB
__device__ float  g_part[KSPLIT * BATCH * DOUT];  // 8 MB fp32 partials
__device__ int    g_cnt[NTILE];                   // zero-init; reset by reducer

// ---------------------------------------------------------------------------
// Helpers
// ---------------------------------------------------------------------------
__device__ __forceinline__ float tanh_ap(float f) {
    float r; asm("tanh.approx.f32 %0, %1;" : "=f"(r) : "f"(f)); return r;
}
__device__ __forceinline__ float sqrt_ap(float f) {
    float r; asm("sqrt.approx.f32 %0, %1;" : "=f"(r) : "f"(f)); return r;
}
__device__ __forceinline__ uint32_t s2u(const void* p) {
    uint32_t a;
    asm("{ .reg .u64 t; cvta.to.shared.u64 t, %1; cvt.u32.u64 %0, t; }" : "=r"(a) : "l"(p));
    return a;
}
__device__ __forceinline__ void cp16(uint32_t dst, const void* src) {
    asm volatile("cp.async.cg.shared.global [%0], [%1], 16;" :: "r"(dst), "l"(src) : "memory");
}
#define CP_COMMIT() asm volatile("cp.async.commit_group;" ::: "memory")
#define CP_WAIT0()  asm volatile("cp.async.wait_group 0;"  ::: "memory")

__device__ __forceinline__ void ldm_x4(uint32_t* r, uint32_t addr) {
    asm volatile("ldmatrix.sync.aligned.m8n8.x4.shared.b16 {%0,%1,%2,%3}, [%4];"
        : "=r"(r[0]), "=r"(r[1]), "=r"(r[2]), "=r"(r[3]) : "r"(addr));
}
__device__ __forceinline__ void ldm_x4t(uint32_t* r, uint32_t addr) {
    asm volatile("ldmatrix.sync.aligned.m8n8.x4.trans.shared.b16 {%0,%1,%2,%3}, [%4];"
        : "=r"(r[0]), "=r"(r[1]), "=r"(r[2]), "=r"(r[3]) : "r"(addr));
}
__device__ __forceinline__ void mma_f16(float* d, const uint32_t* a, uint32_t b0, uint32_t b1) {
    asm volatile(
        "mma.sync.aligned.m16n8k16.row.col.f32.f16.f16.f32 "
        "{%0,%1,%2,%3}, {%4,%5,%6,%7}, {%8,%9}, {%0,%1,%2,%3};"
        : "+f"(d[0]), "+f"(d[1]), "+f"(d[2]), "+f"(d[3])
        : "r"(a[0]), "r"(a[1]), "r"(a[2]), "r"(a[3]), "r"(b0), "r"(b1));
}

// ---------------------------------------------------------------------------
// Prep: g_Wh[o][i*10 + 2p .. 2p+1] = fp16(W[i,o,kb]*C[i,o]); slot 9 = 0.
// ---------------------------------------------------------------------------
__global__ void kan_prep(const float* __restrict__ W, const float* __restrict__ C) {
    int j = blockIdx.x * blockDim.x + threadIdx.x;   // 0 .. 81919
    int p  = j % 5;
    int io = j / 5;                 // i*128 + o
    if (io >= DIN * DOUT) return;
    int o = io & 127;
    int i = io >> 7;
    float cv = C[io];
    const float* wp = W + (size_t)io * NB + p * 2;
    float v0 = wp[0] * cv;
    float v1 = (p < 4) ? wp[1] * cv : 0.0f;
    ((__half2*)g_Wh)[o * (KTOT / 2) + i * (KPAD / 2) + p] = __floats2half2_rn(v0, v1);
}

// ---------------------------------------------------------------------------
// One basis evaluation -> 10 fp16 k-rows of one A stage (CF contiguous stores)
// ---------------------------------------------------------------------------
__device__ __forceinline__ void eval_feat(__half* Ast, int row, int ii, float xv) {
    float ax = fabsf(xv);
    float x2 = xv * xv;
    __half* d = Ast + (ii * KPAD) * ASTR + row;
    d[0 * ASTR] = __float2half_rn(xv);
    d[1 * ASTR] = __float2half_rn(x2);
    d[2 * ASTR] = __float2half_rn(x2 * xv);
    d[3 * ASTR] = __float2half_rn(__expf(xv));
    d[4 * ASTR] = __float2half_rn(__logf(ax + 1.0f));
    d[5 * ASTR] = __float2half_rn(sqrt_ap(ax));
    d[6 * ASTR] = __float2half_rn(tanh_ap(xv));
    d[7 * ASTR] = __float2half_rn(__sinf(xv));
    d[8 * ASTR] = __float2half_rn(ax);
    d[9 * ASTR] = __half(0.0f);
}

// ---------------------------------------------------------------------------
// Main: fused basis + fp16 ldmatrix mma; A double-buffered with produce(c+1)
// overlapping mma(c) in ONE barrier interval; x prefetched to registers;
// split-K=4, fused last-block reduction. Grid (64, 4), 256 thr, 2 CTAs/SM.
// ---------------------------------------------------------------------------
__global__ __launch_bounds__(256, 2)
void kan_main(const float* __restrict__ x, const float* __restrict__ bias,
              const float* __restrict__ C, float* __restrict__ out)
{
    extern __shared__ char smem[];
    __half* Bs = (__half*)(smem + OFF_BS);     // [128 n][328], cols 0..319 data
    __half* As = (__half*)(smem + OFF_AS);     // 2 stages of [80 k][72 m]
    float*  Bp = (float*)(smem + OFF_BP);      // [128] beta partials
    __shared__ int s_last;

    const int tid   = threadIdx.x;
    const int lane  = tid & 31;
    const int warp  = tid >> 5;
    const int wm    = warp & 1;
    const int wn    = warp >> 1;
    const int g     = lane >> 2;
    const int tg    = lane & 3;
    const int t4    = lane >> 3;
    const int r8    = lane & 7;
    const int tile  = blockIdx.x;
    const int split = blockIdx.y;
    const int bm0   = tile * BM;
    const int i0    = split * ISL;

    // feat-task coordinates for this thread (same row for both jj tasks)
    const int frow = tid & 63;
    const int fii0 = tid >> 6;           // task 0: ii = fii0, task 1: ii = fii0+4
    const float* xrow = x + (size_t)(bm0 + frow) * DIN + i0;

    // --- cp.async the fp16 B slice [128 n][320 k]: 5120 x 16B
    {
        const uint32_t bsb = s2u(Bs);
        const __half*  src0 = g_Wh + (size_t)split * KSLICE;
        #pragma unroll
        for (int jj = 0; jj < 20; ++jj) {
            int j = tid + jj * 256;
            int n = j / 40, q = j - n * 40;
            cp16(bsb + (uint32_t)(n * (BSTR * 2) + q * 16),
                 src0 + (size_t)n * KTOT + q * 8);
        }
        CP_COMMIT();
    }

    // --- this split's beta slice
    if (tid < DOUT) {
        float s = 0.0f;
        #pragma unroll 8
        for (int ii = 0; ii < ISL; ++ii)
            s += bias[(i0 + ii) * DOUT + tid] * C[(i0 + ii) * DOUT + tid];
        Bp[tid] = s;
    }

    // --- prefetch x for chunks 0 and 1
    float xc0a = xrow[fii0],          xc0b = xrow[fii0 + 4];
    float xna  = xrow[FCH + fii0],    xnb  = xrow[FCH + fii0 + 4];

    // --- ldmatrix lane base addresses
    uint32_t aAddr[2], bAddr[2];
    {
        const uint32_t asb = s2u(As), bsb = s2u(Bs);
        #pragma unroll
        for (int mt = 0; mt < 2; ++mt) {
            int m0 = wm * 32 + mt * 16;
            aAddr[mt] = asb + (uint32_t)(((t4 >> 1) * 8 + r8) * ASTR + m0 + (t4 & 1) * 8) * 2;
        }
        #pragma unroll
        for (int p = 0; p < 2; ++p) {
            int n = wn * 32 + p * 16 + (t4 >> 1) * 8 + r8;
            bAddr[p] = bsb + (uint32_t)(n * BSTR + (t4 & 1) * 8) * 2;
        }
    }

    float acc[2][4][4];
    #pragma unroll
    for (int mt = 0; mt < 2; ++mt)
        #pragma unroll
        for (int nt = 0; nt < 4; ++nt)
            #pragma unroll
            for (int e = 0; e < 4; ++e) acc[mt][nt][e] = 0.0f;

    // --- chunk 0 feats into stage 0
    eval_feat(As, frow, fii0,     xc0a);
    eval_feat(As, frow, fii0 + 4, xc0b);
    CP_WAIT0();
    __syncthreads();   // stage 0 + B slice + Bp visible

    #pragma unroll
    for (int c = 0; c < NCH; ++c) {
        // --- produce chunk c+1 into the other stage (overlaps this mma interval)
        if (c + 1 < NCH) {
            __half* Ast = As + ((c + 1) & 1) * (AS_STG / 2);
            eval_feat(Ast, frow, fii0,     xna);
            eval_feat(Ast, frow, fii0 + 4, xnb);
            if (c + 2 < NCH) {               // prefetch x for chunk c+2
                xna = xrow[(c + 2) * FCH + fii0];
                xnb = xrow[(c + 2) * FCH + fii0 + 4];
            }
        }

        // --- 5 k16-steps on stage c&1
        const uint32_t aStage = (uint32_t)((c & 1) * AS_STG);
        #pragma unroll
        for (int s5 = 0; s5 < 5; ++s5) {
            const uint32_t kaOff = aStage + (uint32_t)(s5 * 16 * ASTR) * 2;
            const uint32_t kbOff = (uint32_t)((c * KCH + s5 * 16)) * 2;
            uint32_t a[2][4], bq[2][4];
            ldm_x4t(a[0], aAddr[0] + kaOff);
            ldm_x4t(a[1], aAddr[1] + kaOff);
            ldm_x4(bq[0], bAddr[0] + kbOff);
            ldm_x4(bq[1], bAddr[1] + kbOff);
            #pragma unroll
            for (int mt = 0; mt < 2; ++mt)
                #pragma unroll
                for (int nt = 0; nt < 4; ++nt)
                    mma_f16(acc[mt][nt], a[mt],
                            bq[nt >> 1][(nt & 1) * 2], bq[nt >> 1][(nt & 1) * 2 + 1]);
        }
        __syncthreads();   // stage c reads done AND stage c+1 writes done
    }

    // --- epilogue: add beta, write partials
    {
        float* base = g_part + (size_t)split * BATCH * DOUT;
        #pragma unroll
        for (int nt = 0; nt < 4; ++nt) {
            int col = wn * 32 + nt * 8 + tg * 2;
            float b0 = Bp[col];
            float b1 = Bp[col + 1];
            #pragma unroll
            for (int mt = 0; mt < 2; ++mt) {
                int row = bm0 + wm * 32 + mt * 16 + g;
                float* p = base + (size_t)row * DOUT + col;
                *(float2*)p              = make_float2(acc[mt][nt][0] + b0, acc[mt][nt][1] + b1);
                *(float2*)(p + 8 * DOUT) = make_float2(acc[mt][nt][2] + b0, acc[mt][nt][3] + b1);
            }
        }
    }

    // --- last split block of this tile reduces 4 partial planes -> out
    __threadfence();
    __syncthreads();
    if (tid == 0)
        s_last = (atomicAdd(&g_cnt[tile], 1) == KSPLIT - 1);
    __syncthreads();

    if (s_last) {
        __threadfence();
        const float4* pp = (const float4*)g_part;
        const size_t plane = (size_t)BATCH * DOUT / 4;
        const size_t base4 = (size_t)bm0 * (DOUT / 4);
        #pragma unroll
        for (int idx = tid; idx < BM * DOUT / 4; idx += 256) {
            size_t o = base4 + idx;
            float4 p0 = __ldcg(pp + o);
            float4 p1 = __ldcg(pp + plane + o);
            float4 p2 = __ldcg(pp + 2 * plane + o);
            float4 p3 = __ldcg(pp + 3 * plane + o);
            float4 s;
            s.x = (p0.x + p1.x) + (p2.x + p3.x);
            s.y = (p0.y + p1.y) + (p2.y + p3.y);
            s.z = (p0.z + p1.z) + (p2.z + p3.z);
            s.w = (p0.w + p1.w) + (p2.w + p3.w);
            ((float4*)out)[o] = s;
        }
        __syncthreads();
        if (tid == 0) g_cnt[tile] = 0;
    }
}

// ---------------------------------------------------------------------------
extern "C" void kernel_launch(void* const* d_in, const int* in_sizes, int n_in,
                              void* d_out, int out_size) {
    const float* x    = (const float*)d_in[0];   // [4096,128]
    const float* W    = (const float*)d_in[1];   // [128,128,9]
    const float* bias = (const float*)d_in[2];   // [128,128]
    const float* C    = (const float*)d_in[3];   // [128,128]
    float* out        = (float*)d_out;           // [4096,128]
    (void)in_sizes; (void)n_in; (void)out_size;

    cudaFuncSetAttribute(kan_main, cudaFuncAttributeMaxDynamicSharedMemorySize, SMEM_BYTES);

    kan_prep<<<320, 256>>>(W, C);
    kan_main<<<dim3(NTILE, KSPLIT), 256, SMEM_BYTES>>>(x, bias, C, out);
}